// round 8
// baseline (speedup 1.0000x reference)
#include <cuda_runtime.h>

#define N_NODES 50000
#define E_EDGES 800000
#define D 128
#define D4 32      // D in float4 units
#define NPB 32     // nodes per tile
#define NTILES ((N_NODES + NPB - 1) / NPB)
#define GTHREADS 512
#define GGRID 152
#define SROW 65    // float4 row stride for s_in (odd -> conflict-free)

// smem: wl_s[128*32] | wr_s[128*32] | s_in[NPB*SROW] | mu[32] | rs[32]
#define SMEM_F4 (2 * 128 * 32 + NPB * SROW)
#define SMEM_BYTES (SMEM_F4 * 16 + 64 * 4)

// Scratch (allocation-free rule: __device__ globals)
__device__ float4 g_agg[N_NODES * D4];
__device__ float4 g_h1[N_NODES * D4];
__device__ float4 g_h2[N_NODES * D4];
__device__ int    g_deg[N_NODES];
__device__ int    g_rowptr[N_NODES + 1];
__device__ int    g_cursor[N_NODES];
__device__ int    g_csrc[E_EDGES];

// ---------------------------------------------------------------------------
// packed f32x2 helpers
// ---------------------------------------------------------------------------
__device__ __forceinline__ void fma2(unsigned long long& d,
                                     unsigned long long a,
                                     unsigned long long b) {
    asm("fma.rn.f32x2 %0, %1, %2, %0;" : "+l"(d) : "l"(a), "l"(b));
}
__device__ __forceinline__ unsigned long long pack2(float lo, float hi) {
    unsigned long long r;
    asm("mov.b64 %0, {%1, %2};" : "=l"(r) : "f"(lo), "f"(hi));
    return r;
}
__device__ __forceinline__ float sum2(unsigned long long v) {
    float lo, hi;
    asm("mov.b64 {%0, %1}, %2;" : "=f"(lo), "=f"(hi) : "l"(v));
    return lo + hi;
}

// ---------------------------------------------------------------------------
// CSR build: zero degrees -> histogram -> scan -> fill src lists
// ---------------------------------------------------------------------------
__global__ void zero_deg_kernel() {
    int i = blockIdx.x * blockDim.x + threadIdx.x;
    if (i < N_NODES) g_deg[i] = 0;
}

__global__ void hist_kernel(const int* __restrict__ dst, int E) {
    int e = blockIdx.x * blockDim.x + threadIdx.x;
    if (e < E) atomicAdd(&g_deg[__ldg(dst + e)], 1);
}

__device__ __forceinline__ int warp_incl_scan(int v, int lane) {
    #pragma unroll
    for (int o = 1; o < 32; o <<= 1) {
        int t = __shfl_up_sync(0xFFFFFFFFu, v, o);
        if (lane >= o) v += t;
    }
    return v;
}

__global__ void __launch_bounds__(1024) scan_kernel() {
    __shared__ int s_warp[32];
    __shared__ int s_carry;
    int tid = threadIdx.x;
    int lane = tid & 31, wid = tid >> 5;
    if (tid == 0) s_carry = 0;
    __syncthreads();

    for (int base = 0; base < N_NODES; base += 1024) {
        int idx = base + tid;
        int v = (idx < N_NODES) ? g_deg[idx] : 0;
        int incl = warp_incl_scan(v, lane);
        if (lane == 31) s_warp[wid] = incl;
        __syncthreads();
        if (wid == 0) {
            int w = s_warp[lane];
            w = warp_incl_scan(w, lane);
            s_warp[lane] = w;
        }
        __syncthreads();
        int offset = (wid > 0) ? s_warp[wid - 1] : 0;
        int excl = s_carry + offset + incl - v;
        if (idx < N_NODES) {
            g_rowptr[idx] = excl;
            g_cursor[idx] = excl;
        }
        int chunk_total = s_warp[31];
        __syncthreads();
        if (tid == 0) s_carry += chunk_total;
        __syncthreads();
    }
    if (tid == 0) g_rowptr[N_NODES] = s_carry;
}

__global__ void fill_kernel(const int* __restrict__ src,
                            const int* __restrict__ dst, int E) {
    int e = blockIdx.x * blockDim.x + threadIdx.x;
    if (e >= E) return;
    int d = __ldg(dst + e);
    int pos = atomicAdd(&g_cursor[d], 1);
    g_csrc[pos] = __ldg(src + e);
}

// ---------------------------------------------------------------------------
// Aggregate: one warp per node, 16-deep MLP on the gather loads.
// ---------------------------------------------------------------------------
__global__ void __launch_bounds__(256)
aggregate_kernel(const float4* __restrict__ x, float4* __restrict__ agg) {
    int warp = (blockIdx.x * blockDim.x + threadIdx.x) >> 5;
    if (warp >= N_NODES) return;
    int lane = threadIdx.x & 31;
    int beg = __ldg(g_rowptr + warp);
    int end = __ldg(g_rowptr + warp + 1);

    float4 a = make_float4(0.f, 0.f, 0.f, 0.f);
    int i = beg;
    for (; i + 16 <= end; i += 16) {
        int s[16];
        #pragma unroll
        for (int u = 0; u < 16; u++) s[u] = __ldg(g_csrc + i + u);
        float4 v[16];
        #pragma unroll
        for (int u = 0; u < 16; u++) v[u] = __ldg(x + s[u] * D4 + lane);
        #pragma unroll
        for (int u = 0; u < 16; u++) {
            a.x += v[u].x; a.y += v[u].y; a.z += v[u].z; a.w += v[u].w;
        }
    }
    for (; i + 4 <= end; i += 4) {
        int s[4];
        #pragma unroll
        for (int u = 0; u < 4; u++) s[u] = __ldg(g_csrc + i + u);
        float4 v[4];
        #pragma unroll
        for (int u = 0; u < 4; u++) v[u] = __ldg(x + s[u] * D4 + lane);
        #pragma unroll
        for (int u = 0; u < 4; u++) {
            a.x += v[u].x; a.y += v[u].y; a.z += v[u].z; a.w += v[u].w;
        }
    }
    for (; i < end; i++) {
        int s = __ldg(g_csrc + i);
        float4 v = __ldg(x + s * D4 + lane);
        a.x += v.x; a.y += v.y; a.z += v.z; a.w += v.w;
    }
    agg[warp * D4 + lane] = a;
}

// ---------------------------------------------------------------------------
// Persistent GEMM v2: lane = node row, warp = 8 uniform j-columns.
//   Weight LDS are lane-uniform (broadcast, cheap); the one wide LDS per k4
//   is the input row read, conflict-free via SROW=65 padding.
// 512 threads: wj = warp (0..15) -> j0 = wj*8 ; lane = m (node within tile).
// MODE 0: LayerNorm -> ReLU ; MODE 1: ReLU ; MODE 2: identity
// ---------------------------------------------------------------------------
template <int MODE>
__global__ void __launch_bounds__(GTHREADS)
gemm_persist(const float4* __restrict__ agg,
             const float4* __restrict__ hin,
             const float* __restrict__ Wl,
             const float* __restrict__ bl,
             const float* __restrict__ Wr,
             const float* __restrict__ lng,
             const float* __restrict__ lnb,
             float* __restrict__ out) {
    extern __shared__ float4 smem[];
    float4* wl_s = smem;                       // [j*32 + k4], 128*32
    float4* wr_s = smem + 128 * 32;            // [j*32 + k4], 128*32
    float4* s_in = smem + 2 * 128 * 32;        // [m*SROW + q], q:0..63
    float*  s_mu = reinterpret_cast<float*>(s_in + NPB * SROW);
    float*  s_rs = s_mu + NPB;

    const int tid = threadIdx.x;
    const int lane = tid & 31;   // m row
    const int wj = tid >> 5;     // 0..15
    const int j0 = wj * 8;

    // ---- stage full weights once (coalesced, linear layout) ----
    {
        const float4* Wl4 = reinterpret_cast<const float4*>(Wl);
        const float4* Wr4 = reinterpret_cast<const float4*>(Wr);
        #pragma unroll
        for (int idx = tid; idx < 128 * 32; idx += GTHREADS) {
            wl_s[idx] = __ldg(Wl4 + idx);
            wr_s[idx] = __ldg(Wr4 + idx);
        }
    }
    // per-thread j metadata (8 columns)
    unsigned long long bias2[8];
    float lg[8], lb[8];
    #pragma unroll
    for (int jj = 0; jj < 8; jj++) {
        bias2[jj] = pack2(__ldg(bl + j0 + jj), 0.0f);
        lg[jj] = __ldg(lng + j0 + jj);
        lb[jj] = __ldg(lnb + j0 + jj);
    }

    for (int tile = blockIdx.x; tile < NTILES; tile += GGRID) {
        const int n0 = tile * NPB;
        __syncthreads();  // s_in reuse safe (prev tile fully consumed)

        // ---- stage tile inputs: agg rows (q 0..31) + hin rows (q 32..63)
        #pragma unroll
        for (int i = tid; i < NPB * 64; i += GTHREADS) {
            int m = i >> 6, q = i & 63;
            int n = n0 + m;
            if (n >= N_NODES) n = N_NODES - 1;  // clamp
            s_in[m * SROW + q] = (q < 32) ? __ldg(agg + n * D4 + q)
                                          : __ldg(hin + n * D4 + (q - 32));
        }
        __syncthreads();

        unsigned long long acc2[8];
        #pragma unroll
        for (int jj = 0; jj < 8; jj++) acc2[jj] = bias2[jj];

        // ---- mainloop: h=0 Wl x agg, h=1 Wr x hin (all smem) ----
        #pragma unroll 1
        for (int h = 0; h < 2; h++) {
            const float4* ws = h ? wr_s : wl_s;
            const int qb = h * 32;
            #pragma unroll 4
            for (int k4 = 0; k4 < 32; k4++) {
                ulonglong2 v = *reinterpret_cast<const ulonglong2*>(
                                   &s_in[lane * SROW + qb + k4]);
                #pragma unroll
                for (int jj = 0; jj < 8; jj++) {
                    ulonglong2 w = *reinterpret_cast<const ulonglong2*>(
                                       &ws[(j0 + jj) * 32 + k4]);
                    fma2(acc2[jj], w.x, v.x);
                    fma2(acc2[jj], w.y, v.y);
                }
            }
        }

        if (MODE == 0) {
            // LayerNorm over the 128 outputs of each row, then ReLU
            __syncthreads();  // done reading s_in; reuse as row buffer
            float* s_f = reinterpret_cast<float*>(s_in);  // [m][132]
            {
                float4 p0, p1;
                p0.x = sum2(acc2[0]); p0.y = sum2(acc2[1]);
                p0.z = sum2(acc2[2]); p0.w = sum2(acc2[3]);
                p1.x = sum2(acc2[4]); p1.y = sum2(acc2[5]);
                p1.z = sum2(acc2[6]); p1.w = sum2(acc2[7]);
                *reinterpret_cast<float4*>(&s_f[lane * 132 + j0]) = p0;
                *reinterpret_cast<float4*>(&s_f[lane * 132 + j0 + 4]) = p1;
            }
            __syncthreads();

            #pragma unroll
            for (int q = 0; q < 2; q++) {
                int r = wj * 2 + q;
                float v0 = s_f[r * 132 + lane];
                float v1 = s_f[r * 132 + lane + 32];
                float v2 = s_f[r * 132 + lane + 64];
                float v3 = s_f[r * 132 + lane + 96];
                float s  = v0 + v1 + v2 + v3;
                float ss = v0 * v0 + v1 * v1 + v2 * v2 + v3 * v3;
                #pragma unroll
                for (int o = 16; o > 0; o >>= 1) {
                    s  += __shfl_down_sync(0xFFFFFFFFu, s, o);
                    ss += __shfl_down_sync(0xFFFFFFFFu, ss, o);
                }
                if (lane == 0) {
                    float mu  = s * (1.0f / 128.0f);
                    float var = ss * (1.0f / 128.0f) - mu * mu;
                    s_mu[r] = mu;
                    s_rs[r] = rsqrtf(var + 1e-5f);
                }
            }
            __syncthreads();

            int n = n0 + lane;
            if (n < N_NODES) {
                float mu = s_mu[lane], rs = s_rs[lane];
                float4 p0 = *reinterpret_cast<float4*>(&s_f[lane * 132 + j0]);
                float4 p1 = *reinterpret_cast<float4*>(&s_f[lane * 132 + j0 + 4]);
                float4 o0, o1;
                o0.x = fmaxf((p0.x - mu) * rs * lg[0] + lb[0], 0.0f);
                o0.y = fmaxf((p0.y - mu) * rs * lg[1] + lb[1], 0.0f);
                o0.z = fmaxf((p0.z - mu) * rs * lg[2] + lb[2], 0.0f);
                o0.w = fmaxf((p0.w - mu) * rs * lg[3] + lb[3], 0.0f);
                o1.x = fmaxf((p1.x - mu) * rs * lg[4] + lb[4], 0.0f);
                o1.y = fmaxf((p1.y - mu) * rs * lg[5] + lb[5], 0.0f);
                o1.z = fmaxf((p1.z - mu) * rs * lg[6] + lb[6], 0.0f);
                o1.w = fmaxf((p1.w - mu) * rs * lg[7] + lb[7], 0.0f);
                *reinterpret_cast<float4*>(&out[n * D + j0]) = o0;
                *reinterpret_cast<float4*>(&out[n * D + j0 + 4]) = o1;
            }
        } else {
            int n = n0 + lane;
            if (n < N_NODES) {
                float4 o0, o1;
                o0.x = sum2(acc2[0]); o0.y = sum2(acc2[1]);
                o0.z = sum2(acc2[2]); o0.w = sum2(acc2[3]);
                o1.x = sum2(acc2[4]); o1.y = sum2(acc2[5]);
                o1.z = sum2(acc2[6]); o1.w = sum2(acc2[7]);
                if (MODE == 1) {
                    o0.x = fmaxf(o0.x, 0.f); o0.y = fmaxf(o0.y, 0.f);
                    o0.z = fmaxf(o0.z, 0.f); o0.w = fmaxf(o0.w, 0.f);
                    o1.x = fmaxf(o1.x, 0.f); o1.y = fmaxf(o1.y, 0.f);
                    o1.z = fmaxf(o1.z, 0.f); o1.w = fmaxf(o1.w, 0.f);
                }
                *reinterpret_cast<float4*>(&out[n * D + j0]) = o0;
                *reinterpret_cast<float4*>(&out[n * D + j0 + 4]) = o1;
            }
        }
    }
}

// ---------------------------------------------------------------------------
// Launch: CSR build once, then 3 x (aggregate -> persistent gemm)
// ---------------------------------------------------------------------------
extern "C" void kernel_launch(void* const* d_in, const int* in_sizes, int n_in,
                              void* d_out, int out_size) {
    const float4* x   = (const float4*)d_in[0];
    const int*    ei  = (const int*)d_in[1];
    const int E       = in_sizes[1] / 2;
    const int* src = ei;
    const int* dst = ei + E;

    const float* Wl0 = (const float*)d_in[2];
    const float* bl0 = (const float*)d_in[3];
    const float* Wr0 = (const float*)d_in[4];
    const float* Wl1 = (const float*)d_in[5];
    const float* bl1 = (const float*)d_in[6];
    const float* Wr1 = (const float*)d_in[7];
    const float* Wl2 = (const float*)d_in[8];
    const float* bl2 = (const float*)d_in[9];
    const float* Wr2 = (const float*)d_in[10];
    const float* lng = (const float*)d_in[11];
    const float* lnb = (const float*)d_in[12];

    float4 *agg, *h1, *h2;
    cudaGetSymbolAddress((void**)&agg, g_agg);
    cudaGetSymbolAddress((void**)&h1, g_h1);
    cudaGetSymbolAddress((void**)&h2, g_h2);

    float* out = (float*)d_out;

    cudaFuncSetAttribute(gemm_persist<0>, cudaFuncAttributeMaxDynamicSharedMemorySize, SMEM_BYTES);
    cudaFuncSetAttribute(gemm_persist<1>, cudaFuncAttributeMaxDynamicSharedMemorySize, SMEM_BYTES);
    cudaFuncSetAttribute(gemm_persist<2>, cudaFuncAttributeMaxDynamicSharedMemorySize, SMEM_BYTES);

    const int edge_blocks = (E + 255) / 256;
    const int agg_blocks  = (N_NODES * 32 + 255) / 256;  // warp per node

    // ---- CSR build (once; reused by all 3 layers) ----
    zero_deg_kernel<<<(N_NODES + 255) / 256, 256>>>();
    hist_kernel<<<edge_blocks, 256>>>(dst, E);
    scan_kernel<<<1, 1024>>>();
    fill_kernel<<<edge_blocks, 256>>>(src, dst, E);

    // ---- layer 0: conv -> LN -> ReLU ----
    aggregate_kernel<<<agg_blocks, 256>>>(x, agg);
    gemm_persist<0><<<GGRID, GTHREADS, SMEM_BYTES>>>(agg, x, Wl0, bl0, Wr0, lng, lnb, (float*)h1);

    // ---- layer 1: conv -> ReLU ----
    aggregate_kernel<<<agg_blocks, 256>>>((const float4*)h1, agg);
    gemm_persist<1><<<GGRID, GTHREADS, SMEM_BYTES>>>(agg, (const float4*)h1, Wl1, bl1, Wr1, lng, lnb, (float*)h2);

    // ---- layer 2: conv (no activation) ----
    aggregate_kernel<<<agg_blocks, 256>>>((const float4*)h2, agg);
    gemm_persist<2><<<GGRID, GTHREADS, SMEM_BYTES>>>(agg, (const float4*)h2, Wl2, bl2, Wr2, lng, lnb, out);
}

// round 9
// speedup vs baseline: 1.2300x; 1.2300x over previous
#include <cuda_runtime.h>

#define N_NODES 50000
#define E_EDGES 800000
#define D 128
#define D4 32      // D in float4 units
#define NPB 64     // nodes per tile
#define NTILES ((N_NODES + NPB - 1) / NPB)
#define GTHREADS 512
#define GGRID 152
#define WSTRIDE 65 // float4 per j-pair row in weight smem (odd -> conflict-free)

// smem: wl_s[64*65] | wr_s[64*65] | s_in[NPB*64] | mu[64] | rs[64]
#define SMEM_F4 (2 * 64 * WSTRIDE + NPB * 64)
#define SMEM_BYTES (SMEM_F4 * 16 + 128 * 4)

// Scratch (allocation-free rule: __device__ globals)
__device__ float4 g_agg[N_NODES * D4];
__device__ float4 g_h1[N_NODES * D4];
__device__ float4 g_h2[N_NODES * D4];
__device__ int    g_deg[N_NODES];
__device__ int    g_rowptr[N_NODES + 1];
__device__ int    g_cursor[N_NODES];
__device__ int    g_csrc[E_EDGES];

// ---------------------------------------------------------------------------
// packed f32x2 helpers
// ---------------------------------------------------------------------------
__device__ __forceinline__ void fma2(unsigned long long& d,
                                     unsigned long long a,
                                     unsigned long long b) {
    asm("fma.rn.f32x2 %0, %1, %2, %0;" : "+l"(d) : "l"(a), "l"(b));
}
__device__ __forceinline__ unsigned long long pack2(float lo, float hi) {
    unsigned long long r;
    asm("mov.b64 %0, {%1, %2};" : "=l"(r) : "f"(lo), "f"(hi));
    return r;
}
__device__ __forceinline__ float sum2(unsigned long long v) {
    float lo, hi;
    asm("mov.b64 {%0, %1}, %2;" : "=f"(lo), "=f"(hi) : "l"(v));
    return lo + hi;
}

// ---------------------------------------------------------------------------
// CSR build: zero degrees -> histogram -> scan -> fill src lists
// ---------------------------------------------------------------------------
__global__ void zero_deg_kernel() {
    int i = blockIdx.x * blockDim.x + threadIdx.x;
    if (i < N_NODES) g_deg[i] = 0;
}

__global__ void hist_kernel(const int* __restrict__ dst, int E) {
    int e = blockIdx.x * blockDim.x + threadIdx.x;
    if (e < E) atomicAdd(&g_deg[__ldg(dst + e)], 1);
}

__device__ __forceinline__ int warp_incl_scan(int v, int lane) {
    #pragma unroll
    for (int o = 1; o < 32; o <<= 1) {
        int t = __shfl_up_sync(0xFFFFFFFFu, v, o);
        if (lane >= o) v += t;
    }
    return v;
}

__global__ void __launch_bounds__(1024) scan_kernel() {
    __shared__ int s_warp[32];
    __shared__ int s_carry;
    int tid = threadIdx.x;
    int lane = tid & 31, wid = tid >> 5;
    if (tid == 0) s_carry = 0;
    __syncthreads();

    for (int base = 0; base < N_NODES; base += 1024) {
        int idx = base + tid;
        int v = (idx < N_NODES) ? g_deg[idx] : 0;
        int incl = warp_incl_scan(v, lane);
        if (lane == 31) s_warp[wid] = incl;
        __syncthreads();
        if (wid == 0) {
            int w = s_warp[lane];
            w = warp_incl_scan(w, lane);
            s_warp[lane] = w;
        }
        __syncthreads();
        int offset = (wid > 0) ? s_warp[wid - 1] : 0;
        int excl = s_carry + offset + incl - v;
        if (idx < N_NODES) {
            g_rowptr[idx] = excl;
            g_cursor[idx] = excl;
        }
        int chunk_total = s_warp[31];
        __syncthreads();
        if (tid == 0) s_carry += chunk_total;
        __syncthreads();
    }
    if (tid == 0) g_rowptr[N_NODES] = s_carry;
}

__global__ void fill_kernel(const int* __restrict__ src,
                            const int* __restrict__ dst, int E) {
    int e = blockIdx.x * blockDim.x + threadIdx.x;
    if (e >= E) return;
    int d = __ldg(dst + e);
    int pos = atomicAdd(&g_cursor[d], 1);
    g_csrc[pos] = __ldg(src + e);
}

// ---------------------------------------------------------------------------
// Aggregate: one warp per node, 16-deep MLP on the gather loads.
// ---------------------------------------------------------------------------
__global__ void __launch_bounds__(256)
aggregate_kernel(const float4* __restrict__ x, float4* __restrict__ agg) {
    int warp = (blockIdx.x * blockDim.x + threadIdx.x) >> 5;
    if (warp >= N_NODES) return;
    int lane = threadIdx.x & 31;
    int beg = __ldg(g_rowptr + warp);
    int end = __ldg(g_rowptr + warp + 1);

    float4 a = make_float4(0.f, 0.f, 0.f, 0.f);
    int i = beg;
    for (; i + 16 <= end; i += 16) {
        int s[16];
        #pragma unroll
        for (int u = 0; u < 16; u++) s[u] = __ldg(g_csrc + i + u);
        float4 v[16];
        #pragma unroll
        for (int u = 0; u < 16; u++) v[u] = __ldg(x + s[u] * D4 + lane);
        #pragma unroll
        for (int u = 0; u < 16; u++) {
            a.x += v[u].x; a.y += v[u].y; a.z += v[u].z; a.w += v[u].w;
        }
    }
    for (; i + 4 <= end; i += 4) {
        int s[4];
        #pragma unroll
        for (int u = 0; u < 4; u++) s[u] = __ldg(g_csrc + i + u);
        float4 v[4];
        #pragma unroll
        for (int u = 0; u < 4; u++) v[u] = __ldg(x + s[u] * D4 + lane);
        #pragma unroll
        for (int u = 0; u < 4; u++) {
            a.x += v[u].x; a.y += v[u].y; a.z += v[u].z; a.w += v[u].w;
        }
    }
    for (; i < end; i++) {
        int s = __ldg(g_csrc + i);
        float4 v = __ldg(x + s * D4 + lane);
        a.x += v.x; a.y += v.y; a.z += v.z; a.w += v.w;
    }
    agg[warp * D4 + lane] = a;
}

// ---------------------------------------------------------------------------
// Persistent GEMM (R7 mapping, NPB=64, 8 m-rows per thread):
//   jh = tid & 63 (lane-distinct j pair -> wide weight LDS),
//   mg = tid >> 6 (warp-uniform m-group -> broadcast input LDS).
// Full Wl+Wr resident in smem; grid-strides over 782 node tiles.
// MODE 0: LayerNorm -> ReLU ; MODE 1: ReLU ; MODE 2: identity
// ---------------------------------------------------------------------------
template <int MODE>
__global__ void __launch_bounds__(GTHREADS)
gemm_persist(const float4* __restrict__ agg,
             const float4* __restrict__ hin,
             const float* __restrict__ Wl,
             const float* __restrict__ bl,
             const float* __restrict__ Wr,
             const float* __restrict__ lng,
             const float* __restrict__ lnb,
             float* __restrict__ out) {
    extern __shared__ float4 smem[];
    float4* wl_s = smem;                       // 64 * WSTRIDE
    float4* wr_s = smem + 64 * WSTRIDE;        // 64 * WSTRIDE
    float4* s_in = smem + 2 * 64 * WSTRIDE;    // NPB * 64
    float*  s_mu = reinterpret_cast<float*>(s_in + NPB * 64);
    float*  s_rs = s_mu + NPB;

    const int tid = threadIdx.x;
    const int jh = tid & 63;
    const int j0 = 2 * jh;
    const int mg = tid >> 6;       // 0..7
    const int mbase = mg * 8;
    const int lane = tid & 31;

    // ---- stage full weights once (coalesced, interleaved j-pair layout) ----
    {
        const float4* Wl4 = reinterpret_cast<const float4*>(Wl);
        const float4* Wr4 = reinterpret_cast<const float4*>(Wr);
        #pragma unroll
        for (int idx = tid; idx < 128 * 32; idx += GTHREADS) {
            int j = idx >> 5, k4 = idx & 31;
            int soff = (j >> 1) * WSTRIDE + 2 * k4 + (j & 1);
            wl_s[soff] = __ldg(Wl4 + idx);
            wr_s[soff] = __ldg(Wr4 + idx);
        }
    }
    const unsigned long long bias_a = pack2(__ldg(bl + j0), 0.0f);
    const unsigned long long bias_b = pack2(__ldg(bl + j0 + 1), 0.0f);
    const float ga = __ldg(lng + j0), gb = __ldg(lng + j0 + 1);
    const float ba = __ldg(lnb + j0), bb = __ldg(lnb + j0 + 1);

    const ulonglong2* s_u = reinterpret_cast<const ulonglong2*>(s_in);

    for (int tile = blockIdx.x; tile < NTILES; tile += GGRID) {
        const int n0 = tile * NPB;
        __syncthreads();  // protect s_in reuse

        // ---- stage tile inputs: agg rows (cols 0..31) + hin rows (32..63)
        #pragma unroll
        for (int i = tid; i < NPB * 64; i += GTHREADS) {
            int m = i >> 6, q = i & 63;
            int n = n0 + m;
            if (n >= N_NODES) n = N_NODES - 1;  // clamp
            s_in[i] = (q < 32) ? __ldg(agg + n * D4 + q)
                               : __ldg(hin + n * D4 + (q - 32));
        }
        __syncthreads();

        unsigned long long acc2[8][2];
        #pragma unroll
        for (int m = 0; m < 8; m++) { acc2[m][0] = bias_a; acc2[m][1] = bias_b; }

        // ---- mainloop: Wl x agg, then Wr x hin (all operands in smem)
        #pragma unroll 4
        for (int k4 = 0; k4 < 32; k4++) {
            ulonglong2 wa = *reinterpret_cast<const ulonglong2*>(&wl_s[jh * WSTRIDE + 2 * k4]);
            ulonglong2 wb = *reinterpret_cast<const ulonglong2*>(&wl_s[jh * WSTRIDE + 2 * k4 + 1]);
            #pragma unroll
            for (int m = 0; m < 8; m++) {
                ulonglong2 v = s_u[(mbase + m) * 64 + k4];
                fma2(acc2[m][0], wa.x, v.x);
                fma2(acc2[m][0], wa.y, v.y);
                fma2(acc2[m][1], wb.x, v.x);
                fma2(acc2[m][1], wb.y, v.y);
            }
        }
        #pragma unroll 4
        for (int k4 = 0; k4 < 32; k4++) {
            ulonglong2 wa = *reinterpret_cast<const ulonglong2*>(&wr_s[jh * WSTRIDE + 2 * k4]);
            ulonglong2 wb = *reinterpret_cast<const ulonglong2*>(&wr_s[jh * WSTRIDE + 2 * k4 + 1]);
            #pragma unroll
            for (int m = 0; m < 8; m++) {
                ulonglong2 v = s_u[(mbase + m) * 64 + 32 + k4];
                fma2(acc2[m][0], wa.x, v.x);
                fma2(acc2[m][0], wa.y, v.y);
                fma2(acc2[m][1], wb.x, v.x);
                fma2(acc2[m][1], wb.y, v.y);
            }
        }

        if (MODE == 0) {
            // LayerNorm over the 128 outputs of each row, then ReLU
            __syncthreads();  // done reading s_in; reuse as row buffer
            float* s_f = reinterpret_cast<float*>(s_in);  // [node][132]
            #pragma unroll
            for (int m = 0; m < 8; m++) {
                float2 p = make_float2(sum2(acc2[m][0]), sum2(acc2[m][1]));
                *reinterpret_cast<float2*>(&s_f[(mbase + m) * 132 + j0]) = p;
            }
            __syncthreads();

            int wid = tid >> 5;  // 0..15, each handles 4 rows
            #pragma unroll
            for (int q = 0; q < 4; q++) {
                int r = wid * 4 + q;
                float v0 = s_f[r * 132 + lane];
                float v1 = s_f[r * 132 + lane + 32];
                float v2 = s_f[r * 132 + lane + 64];
                float v3 = s_f[r * 132 + lane + 96];
                float s  = v0 + v1 + v2 + v3;
                float ss = v0 * v0 + v1 * v1 + v2 * v2 + v3 * v3;
                #pragma unroll
                for (int o = 16; o > 0; o >>= 1) {
                    s  += __shfl_down_sync(0xFFFFFFFFu, s, o);
                    ss += __shfl_down_sync(0xFFFFFFFFu, ss, o);
                }
                if (lane == 0) {
                    float mu  = s * (1.0f / 128.0f);
                    float var = ss * (1.0f / 128.0f) - mu * mu;
                    s_mu[r] = mu;
                    s_rs[r] = rsqrtf(var + 1e-5f);
                }
            }
            __syncthreads();

            #pragma unroll
            for (int m = 0; m < 8; m++) {
                int n = n0 + mbase + m;
                if (n < N_NODES) {
                    int r = mbase + m;
                    float2 p = *reinterpret_cast<float2*>(&s_f[r * 132 + j0]);
                    float va = fmaxf((p.x - s_mu[r]) * s_rs[r] * ga + ba, 0.0f);
                    float vb = fmaxf((p.y - s_mu[r]) * s_rs[r] * gb + bb, 0.0f);
                    *reinterpret_cast<float2*>(&out[n * D + j0]) = make_float2(va, vb);
                }
            }
        } else {
            #pragma unroll
            for (int m = 0; m < 8; m++) {
                int n = n0 + mbase + m;
                if (n < N_NODES) {
                    float va = sum2(acc2[m][0]);
                    float vb = sum2(acc2[m][1]);
                    if (MODE == 1) { va = fmaxf(va, 0.0f); vb = fmaxf(vb, 0.0f); }
                    *reinterpret_cast<float2*>(&out[n * D + j0]) = make_float2(va, vb);
                }
            }
        }
    }
}

// ---------------------------------------------------------------------------
// Launch: CSR build once, then 3 x (aggregate -> persistent gemm)
// ---------------------------------------------------------------------------
extern "C" void kernel_launch(void* const* d_in, const int* in_sizes, int n_in,
                              void* d_out, int out_size) {
    const float4* x   = (const float4*)d_in[0];
    const int*    ei  = (const int*)d_in[1];
    const int E       = in_sizes[1] / 2;
    const int* src = ei;
    const int* dst = ei + E;

    const float* Wl0 = (const float*)d_in[2];
    const float* bl0 = (const float*)d_in[3];
    const float* Wr0 = (const float*)d_in[4];
    const float* Wl1 = (const float*)d_in[5];
    const float* bl1 = (const float*)d_in[6];
    const float* Wr1 = (const float*)d_in[7];
    const float* Wl2 = (const float*)d_in[8];
    const float* bl2 = (const float*)d_in[9];
    const float* Wr2 = (const float*)d_in[10];
    const float* lng = (const float*)d_in[11];
    const float* lnb = (const float*)d_in[12];

    float4 *agg, *h1, *h2;
    cudaGetSymbolAddress((void**)&agg, g_agg);
    cudaGetSymbolAddress((void**)&h1, g_h1);
    cudaGetSymbolAddress((void**)&h2, g_h2);

    float* out = (float*)d_out;

    cudaFuncSetAttribute(gemm_persist<0>, cudaFuncAttributeMaxDynamicSharedMemorySize, SMEM_BYTES);
    cudaFuncSetAttribute(gemm_persist<1>, cudaFuncAttributeMaxDynamicSharedMemorySize, SMEM_BYTES);
    cudaFuncSetAttribute(gemm_persist<2>, cudaFuncAttributeMaxDynamicSharedMemorySize, SMEM_BYTES);

    const int edge_blocks = (E + 255) / 256;
    const int agg_blocks  = (N_NODES * 32 + 255) / 256;  // warp per node

    // ---- CSR build (once; reused by all 3 layers) ----
    zero_deg_kernel<<<(N_NODES + 255) / 256, 256>>>();
    hist_kernel<<<edge_blocks, 256>>>(dst, E);
    scan_kernel<<<1, 1024>>>();
    fill_kernel<<<edge_blocks, 256>>>(src, dst, E);

    // ---- layer 0: conv -> LN -> ReLU ----
    aggregate_kernel<<<agg_blocks, 256>>>(x, agg);
    gemm_persist<0><<<GGRID, GTHREADS, SMEM_BYTES>>>(agg, x, Wl0, bl0, Wr0, lng, lnb, (float*)h1);

    // ---- layer 1: conv -> ReLU ----
    aggregate_kernel<<<agg_blocks, 256>>>((const float4*)h1, agg);
    gemm_persist<1><<<GGRID, GTHREADS, SMEM_BYTES>>>(agg, (const float4*)h1, Wl1, bl1, Wr1, lng, lnb, (float*)h2);

    // ---- layer 2: conv (no activation) ----
    aggregate_kernel<<<agg_blocks, 256>>>((const float4*)h2, agg);
    gemm_persist<2><<<GGRID, GTHREADS, SMEM_BYTES>>>(agg, (const float4*)h2, Wl2, bl2, Wr2, lng, lnb, out);
}